// round 2
// baseline (speedup 1.0000x reference)
#include <cuda_runtime.h>
#include <cuda_bf16.h>

// y[n] = beta_0 + sum_{i<7,j<64} x[n,i,j] * w[i,j],  w = gamma^T @ alpha (rank 64)
// x: [131072, 7, 64] fp32.  HBM-bound: 235 MB read -> ~34us floor at ~7TB/s achieved.

#define N_GAMMA 7
#define N_ALPHA 64
#define RANK    64
#define W_ELEMS (N_GAMMA * N_ALPHA)   // 448
#define W_F4    (W_ELEMS / 4)         // 112
#define ROWS_PER_WARP 8
#define WARPS_PER_BLOCK 8

__device__ float g_w[W_ELEMS];

// Collapse CP factors into the 7x64 weight matrix. One block, 448 threads.
__global__ void prep_w_kernel(const float* __restrict__ gamma,   // [64,7]
                              const float* __restrict__ alpha)   // [64,64]
{
    int idx = threadIdx.x;
    if (idx >= W_ELEMS) return;
    int i = idx / N_ALPHA;
    int j = idx % N_ALPHA;
    float s = 0.0f;
#pragma unroll
    for (int r = 0; r < RANK; r++)
        s = fmaf(gamma[r * N_GAMMA + i], alpha[r * N_ALPHA + j], s);
    g_w[idx] = s;
}

__device__ __forceinline__ float fma4(float acc, float4 v, float4 w) {
    acc = fmaf(v.x, w.x, acc);
    acc = fmaf(v.y, w.y, acc);
    acc = fmaf(v.z, w.z, acc);
    acc = fmaf(v.w, w.w, acc);
    return acc;
}

// One warp handles 8 consecutive rows; w held in per-lane registers.
__global__ __launch_bounds__(256) void cp_dot_kernel(
    const float* __restrict__ x,
    const float* __restrict__ beta0_p,
    float* __restrict__ y,
    int n_rows)
{
    int warp = threadIdx.x >> 5;
    int lane = threadIdx.x & 31;
    int wglob = blockIdx.x * WARPS_PER_BLOCK + warp;
    int n0 = wglob * ROWS_PER_WARP;
    if (n0 >= n_rows) return;

    // Per-lane w slice (loop-invariant). Lane >= 16 has a zero tail slice.
    const float4* wg4 = reinterpret_cast<const float4*>(g_w);
    float4 wr0 = wg4[lane];
    float4 wr1 = wg4[32 + lane];
    float4 wr2 = wg4[64 + lane];
    float4 wr3 = (lane < 16) ? wg4[96 + lane] : make_float4(0.f, 0.f, 0.f, 0.f);

    float beta0 = beta0_p[0];
    float outv = 0.0f;

#pragma unroll
    for (int k = 0; k < ROWS_PER_WARP; k += 2) {
        const float4* xa = reinterpret_cast<const float4*>(x + (size_t)(n0 + k)     * W_ELEMS);
        const float4* xb = reinterpret_cast<const float4*>(x + (size_t)(n0 + k + 1) * W_ELEMS);

        // Batch all 8 independent 16B loads up front (MLP).
        float4 a0 = __ldcs(xa + lane);
        float4 a1 = __ldcs(xa + 32 + lane);
        float4 a2 = __ldcs(xa + 64 + lane);
        float4 b0 = __ldcs(xb + lane);
        float4 b1 = __ldcs(xb + 32 + lane);
        float4 b2 = __ldcs(xb + 64 + lane);
        float4 a3 = make_float4(0.f, 0.f, 0.f, 0.f);
        float4 b3 = make_float4(0.f, 0.f, 0.f, 0.f);
        if (lane < 16) {
            a3 = __ldcs(xa + 96 + lane);
            b3 = __ldcs(xb + 96 + lane);
        }

        float accA = 0.f, accB = 0.f;
        accA = fma4(accA, a0, wr0);
        accB = fma4(accB, b0, wr0);
        accA = fma4(accA, a1, wr1);
        accB = fma4(accB, b1, wr1);
        accA = fma4(accA, a2, wr2);
        accB = fma4(accB, b2, wr2);
        accA = fma4(accA, a3, wr3);
        accB = fma4(accB, b3, wr3);

        // Interleaved butterfly reductions (independent chains).
#pragma unroll
        for (int o = 16; o > 0; o >>= 1) {
            accA += __shfl_xor_sync(0xFFFFFFFFu, accA, o);
            accB += __shfl_xor_sync(0xFFFFFFFFu, accB, o);
        }

        if (lane == k)     outv = beta0 + accA;
        if (lane == k + 1) outv = beta0 + accB;
    }

    // One coalesced 32B store per warp.
    if (lane < ROWS_PER_WARP && n0 + lane < n_rows)
        y[n0 + lane] = outv;
}

extern "C" void kernel_launch(void* const* d_in, const int* in_sizes, int n_in,
                              void* d_out, int out_size)
{
    const float* x     = (const float*)d_in[0];
    const float* beta0 = (const float*)d_in[1];
    const float* gamma = (const float*)d_in[2];
    const float* alpha = (const float*)d_in[3];
    float* y = (float*)d_out;

    int n_rows = in_sizes[0] / W_ELEMS;

    prep_w_kernel<<<1, W_ELEMS>>>(gamma, alpha);

    int rows_per_block = WARPS_PER_BLOCK * ROWS_PER_WARP;  // 64
    int grid = (n_rows + rows_per_block - 1) / rows_per_block;
    cp_dot_kernel<<<grid, 256>>>(x, beta0, y, n_rows);
}

// round 3
// speedup vs baseline: 1.0409x; 1.0409x over previous
#include <cuda_runtime.h>
#include <cuda_bf16.h>

// y[n] = beta_0 + sum_{i<7,j<64} x[n,i,j] * w[i,j],  w = gamma^T @ alpha (rank 64)
// x: [131072, 7, 64] fp32.  HBM-bound: 235 MB read -> ~34us floor.
// 2 rows per warp = 896 floats = 224 float4 = exactly 7 full-width warp loads.

#define N_GAMMA 7
#define N_ALPHA 64
#define RANK    64
#define W_ELEMS (N_GAMMA * N_ALPHA)   // 448
#define W_F4    (W_ELEMS / 4)         // 112
#define ROWS_PER_WARP 2
#define WARPS_PER_BLOCK 8

__device__ float g_w[W_ELEMS];

// Collapse CP factors into the 7x64 weight matrix. One block, 448 threads.
__global__ void prep_w_kernel(const float* __restrict__ gamma,   // [64,7]
                              const float* __restrict__ alpha)   // [64,64]
{
    int idx = threadIdx.x;
    if (idx >= W_ELEMS) return;
    int i = idx / N_ALPHA;
    int j = idx % N_ALPHA;
    float s = 0.0f;
#pragma unroll
    for (int r = 0; r < RANK; r++)
        s = fmaf(gamma[r * N_GAMMA + i], alpha[r * N_ALPHA + j], s);
    g_w[idx] = s;
}

__device__ __forceinline__ float fma4(float acc, float4 v, float4 w) {
    acc = fmaf(v.x, w.x, acc);
    acc = fmaf(v.y, w.y, acc);
    acc = fmaf(v.z, w.z, acc);
    acc = fmaf(v.w, w.w, acc);
    return acc;
}

__global__ __launch_bounds__(256) void cp_dot_kernel(
    const float* __restrict__ x,
    const float* __restrict__ beta0_p,
    float* __restrict__ y,
    int n_rows)
{
    __shared__ float4 sw[W_F4];

    // Stage w (1792B) into shared.
    const float4* wg4 = reinterpret_cast<const float4*>(g_w);
    if (threadIdx.x < W_F4)
        sw[threadIdx.x] = wg4[threadIdx.x];
    __syncthreads();

    int warp = threadIdx.x >> 5;
    int lane = threadIdx.x & 31;
    int n0 = (blockIdx.x * WARPS_PER_BLOCK + warp) * ROWS_PER_WARP;
    if (n0 >= n_rows) return;

    const float4* xr = reinterpret_cast<const float4*>(x + (size_t)n0 * W_ELEMS);

    // 7 independent full-width 16B loads (224 float4 = 2 rows, perfectly coalesced).
    float4 v0 = xr[lane];
    float4 v1 = xr[lane + 32];
    float4 v2 = xr[lane + 64];
    float4 v3 = xr[lane + 96];
    float4 v4 = xr[lane + 128];
    float4 v5 = xr[lane + 160];
    float4 v6 = xr[lane + 192];

    // w4 index = (lane + 32t) % 112 ; element belongs to row A if (lane+32t) < 112.
    float accA = 0.f, accB = 0.f;
    accA = fma4(accA, v0, sw[lane]);
    accA = fma4(accA, v1, sw[lane + 32]);
    accA = fma4(accA, v2, sw[lane + 64]);
    {   // t=3: lanes 0-15 -> row A (w idx lane+96); lanes 16-31 -> row B (w idx lane-16)
        float4 w3 = sw[(lane < 16) ? (lane + 96) : (lane - 16)];
        float d = 0.f;
        d = fma4(d, v3, w3);
        if (lane < 16) accA += d; else accB += d;
    }
    accB = fma4(accB, v4, sw[lane + 16]);
    accB = fma4(accB, v5, sw[lane + 48]);
    accB = fma4(accB, v6, sw[lane + 80]);

    // Two interleaved butterfly reductions.
#pragma unroll
    for (int o = 16; o > 0; o >>= 1) {
        accA += __shfl_xor_sync(0xFFFFFFFFu, accA, o);
        accB += __shfl_xor_sync(0xFFFFFFFFu, accB, o);
    }

    if (lane < ROWS_PER_WARP && n0 + lane < n_rows) {
        float r = (lane == 0) ? accA : accB;
        y[n0 + lane] = beta0_p[0] + r;
    }
}

extern "C" void kernel_launch(void* const* d_in, const int* in_sizes, int n_in,
                              void* d_out, int out_size)
{
    const float* x     = (const float*)d_in[0];
    const float* beta0 = (const float*)d_in[1];
    const float* gamma = (const float*)d_in[2];
    const float* alpha = (const float*)d_in[3];
    float* y = (float*)d_out;

    int n_rows = in_sizes[0] / W_ELEMS;

    prep_w_kernel<<<1, W_ELEMS>>>(gamma, alpha);

    int rows_per_block = WARPS_PER_BLOCK * ROWS_PER_WARP;  // 16
    int grid = (n_rows + rows_per_block - 1) / rows_per_block;
    cp_dot_kernel<<<grid, 256>>>(x, beta0, y, n_rows);
}